// round 1
// baseline (speedup 1.0000x reference)
#include <cuda_runtime.h>

// MoreauTropicalKernel: B=128, N=512, D=1024.
// One warp per (b,n) pair; z = x[b]+W[n] resident in registers as 16 packed f32x2.
// Bisection via sum|z-mid| identity + packed add.rn.f32x2; y is stationary in tau
// so 18 steps suffice (y-error is second-order in tau-error).

#define DDIM 1024
#define NDIM 512
#define NBIS 18

__device__ __forceinline__ unsigned long long f32x2_add(unsigned long long a, unsigned long long b) {
    unsigned long long r;
    asm("add.rn.f32x2 %0, %1, %2;" : "=l"(r) : "l"(a), "l"(b));
    return r;
}
__device__ __forceinline__ unsigned long long pack2(float lo, float hi) {
    unsigned long long r;
    asm("mov.b64 %0, {%1, %2};" : "=l"(r) : "f"(lo), "f"(hi));
    return r;
}
__device__ __forceinline__ float2 unpack2(unsigned long long v) {
    float2 r;
    asm("mov.b64 {%0, %1}, %2;" : "=f"(r.x), "=f"(r.y) : "l"(v));
    return r;
}

__global__ __launch_bounds__(256)
void moreau_tropical_kernel(const float* __restrict__ x,
                            const float* __restrict__ W,
                            const float* __restrict__ lamp,
                            float* __restrict__ y,
                            int total_pairs) {
    int warp = (blockIdx.x * 256 + threadIdx.x) >> 5;
    if (warp >= total_pairs) return;
    int lane = threadIdx.x & 31;
    int b = warp >> 9;           // / NDIM
    int n = warp & (NDIM - 1);
    float lam = __ldg(lamp);

    const float4* xr = (const float4*)(x + (size_t)b * DDIM);
    const float4* wr = (const float4*)(W + (size_t)n * DDIM);

    unsigned long long z[16];
    float S = 0.f, mn = 3.4e38f, mx = -3.4e38f;
#pragma unroll
    for (int j = 0; j < 8; j++) {
        float4 xv = xr[lane + 32 * j];
        float4 wv = wr[lane + 32 * j];
        float z0 = xv.x + wv.x;
        float z1 = xv.y + wv.y;
        float z2 = xv.z + wv.z;
        float z3 = xv.w + wv.w;
        z[2 * j]     = pack2(z0, z1);
        z[2 * j + 1] = pack2(z2, z3);
        S += (z0 + z1) + (z2 + z3);
        mn = fminf(mn, fminf(fminf(z0, z1), fminf(z2, z3)));
        mx = fmaxf(mx, fmaxf(fmaxf(z0, z1), fmaxf(z2, z3)));
    }
#pragma unroll
    for (int o = 16; o > 0; o >>= 1) {
        S  += __shfl_xor_sync(0xffffffffu, S, o);
        mn = fminf(mn, __shfl_xor_sync(0xffffffffu, mn, o));
        mx = fmaxf(mx, __shfl_xor_sync(0xffffffffu, mx, o));
    }

    float lo = mn - lam;
    float hi = mx;
    // f(mid) > lam  <=>  sum|z-mid| > 2*lam - S + D*mid
    float C = 2.f * lam - S;

#pragma unroll 1
    for (int it = 0; it < NBIS; it++) {
        float mid = 0.5f * (lo + hi);
        unsigned long long nm = pack2(-mid, -mid);
        unsigned long long a0 = 0ull, a1 = 0ull, a2 = 0ull, a3 = 0ull;
#pragma unroll
        for (int j = 0; j < 16; j += 4) {
            unsigned long long t0 = f32x2_add(z[j + 0], nm) & 0x7FFFFFFF7FFFFFFFULL;
            unsigned long long t1 = f32x2_add(z[j + 1], nm) & 0x7FFFFFFF7FFFFFFFULL;
            unsigned long long t2 = f32x2_add(z[j + 2], nm) & 0x7FFFFFFF7FFFFFFFULL;
            unsigned long long t3 = f32x2_add(z[j + 3], nm) & 0x7FFFFFFF7FFFFFFFULL;
            a0 = f32x2_add(a0, t0);
            a1 = f32x2_add(a1, t1);
            a2 = f32x2_add(a2, t2);
            a3 = f32x2_add(a3, t3);
        }
        a0 = f32x2_add(a0, a1);
        a2 = f32x2_add(a2, a3);
        a0 = f32x2_add(a0, a2);
        float2 av = unpack2(a0);
        float A = av.x + av.y;
#pragma unroll
        for (int o = 16; o > 0; o >>= 1)
            A += __shfl_xor_sync(0xffffffffu, A, o);
        bool low = A > fmaf(1024.f, mid, C);
        lo = low ? mid : lo;
        hi = low ? hi : mid;
    }

    float tau = 0.5f * (lo + hi);
    float dsum = 0.f;
#pragma unroll
    for (int j = 0; j < 16; j++) {
        float2 zv = unpack2(z[j]);
        float t0 = fmaxf(zv.x - tau, 0.f);
        float t1 = fmaxf(zv.y - tau, 0.f);
        dsum = fmaf(t0, t0, dsum);
        dsum = fmaf(t1, t1, dsum);
    }
#pragma unroll
    for (int o = 16; o > 0; o >>= 1)
        dsum += __shfl_xor_sync(0xffffffffu, dsum, o);

    if (lane == 0)
        y[warp] = tau + dsum / (2.f * lam);
}

extern "C" void kernel_launch(void* const* d_in, const int* in_sizes, int n_in,
                              void* d_out, int out_size) {
    const float* x   = (const float*)d_in[0];
    const float* W   = (const float*)d_in[1];
    const float* lam = (const float*)d_in[2];
    float* y = (float*)d_out;

    int B = in_sizes[0] / DDIM;      // 128
    int N = in_sizes[1] / DDIM;      // 512 (kernel index math assumes 512)
    int pairs = B * N;               // 65536
    int blocks = (pairs + 7) / 8;    // 8 warps / block
    moreau_tropical_kernel<<<blocks, 256>>>(x, W, lam, y, pairs);
}

// round 2
// speedup vs baseline: 2.0584x; 2.0584x over previous
#include <cuda_runtime.h>

// MoreauTropicalKernel: B=128, N=512, D=1024. One warp per (b,n) pair.
// z = x[b]+W[n] resident in registers as 16 packed f32x2.
// Key ideas:
//  - f(tau) = sum relu(z-tau); identity f(mid) = 0.5*(sum|z-mid| + S - D*mid)
//    -> per element per step: packed sub + 64b abs-mask + packed acc (2 issue/elem).
//  - Tight bracket: tau* in [max z - lam, max z] (width lam) -> 6 bisect steps.
//  - y = tau + delta is stationary in tau; apply exact-segment Newton correction
//    y* = y(tau) - (lam - fT)^2 / (2*lam*m), m from free finite difference
//    against f at the last bisection midpoint.

#define DDIM 1024
#define NDIM 512
#define NBIS 6

__device__ __forceinline__ unsigned long long f32x2_add(unsigned long long a, unsigned long long b) {
    unsigned long long r;
    asm("add.rn.f32x2 %0, %1, %2;" : "=l"(r) : "l"(a), "l"(b));
    return r;
}
__device__ __forceinline__ unsigned long long pack2(float lo, float hi) {
    unsigned long long r;
    asm("mov.b64 %0, {%1, %2};" : "=l"(r) : "f"(lo), "f"(hi));
    return r;
}
__device__ __forceinline__ float2 unpack2(unsigned long long v) {
    float2 r;
    asm("mov.b64 {%0, %1}, %2;" : "=f"(r.x), "=f"(r.y) : "l"(v));
    return r;
}

__global__ __launch_bounds__(256)
void moreau_tropical_kernel(const float* __restrict__ x,
                            const float* __restrict__ W,
                            const float* __restrict__ lamp,
                            float* __restrict__ y,
                            int total_pairs) {
    int warp = (blockIdx.x * 256 + threadIdx.x) >> 5;
    if (warp >= total_pairs) return;
    int lane = threadIdx.x & 31;
    int b = warp >> 9;           // / NDIM
    int n = warp & (NDIM - 1);
    float lam = __ldg(lamp);

    const float4* xr = (const float4*)(x + (size_t)b * DDIM);
    const float4* wr = (const float4*)(W + (size_t)n * DDIM);

    unsigned long long z[16];
    unsigned long long Sp0 = 0ull, Sp1 = 0ull;
    float mx = -3.4e38f;
#pragma unroll
    for (int j = 0; j < 8; j++) {
        float4 xv = xr[lane + 32 * j];
        float4 wv = wr[lane + 32 * j];
        unsigned long long zp0 = f32x2_add(pack2(xv.x, xv.y), pack2(wv.x, wv.y));
        unsigned long long zp1 = f32x2_add(pack2(xv.z, xv.w), pack2(wv.z, wv.w));
        z[2 * j]     = zp0;
        z[2 * j + 1] = zp1;
        Sp0 = f32x2_add(Sp0, zp0);
        Sp1 = f32x2_add(Sp1, zp1);
        float2 a = unpack2(zp0);
        float2 c = unpack2(zp1);
        mx = fmaxf(mx, fmaxf(fmaxf(a.x, a.y), fmaxf(c.x, c.y)));
    }
    float2 sv = unpack2(f32x2_add(Sp0, Sp1));
    float S = sv.x + sv.y;
#pragma unroll
    for (int o = 16; o > 0; o >>= 1) {
        S  += __shfl_xor_sync(0xffffffffu, S, o);
        mx = fmaxf(mx, __shfl_xor_sync(0xffffffffu, mx, o));
    }

    // Tight bracket: f(mx - lam) >= lam >= f(mx)
    float lo = mx - lam;
    float hi = mx;
    // f(mid) > lam  <=>  A = sum|z-mid| > 2*lam - S + D*mid
    float C = 2.f * lam - S;

    float A = 0.f, mid = lo;
#pragma unroll 1
    for (int it = 0; it < NBIS; it++) {
        mid = 0.5f * (lo + hi);
        unsigned long long nm = pack2(-mid, -mid);
        unsigned long long a0 = 0ull, a1 = 0ull;
#pragma unroll
        for (int j = 0; j < 16; j += 2) {
            unsigned long long t0 = f32x2_add(z[j + 0], nm) & 0x7FFFFFFF7FFFFFFFULL;
            unsigned long long t1 = f32x2_add(z[j + 1], nm) & 0x7FFFFFFF7FFFFFFFULL;
            a0 = f32x2_add(a0, t0);
            a1 = f32x2_add(a1, t1);
        }
        float2 av = unpack2(f32x2_add(a0, a1));
        A = av.x + av.y;
#pragma unroll
        for (int o = 16; o > 0; o >>= 1)
            A += __shfl_xor_sync(0xffffffffu, A, o);
        bool low = A > fmaf(1024.f, mid, C);
        lo = low ? mid : lo;
        hi = low ? hi : mid;
    }

    float tau = 0.5f * (lo + hi);
    // f at the last bisection midpoint, from the already-reduced A (free):
    float fL = 0.5f * (A + S) - 512.f * mid;

    // Epilogue: direct relu pass for dsum (= sum slack^2) and fT (= sum slack)
    unsigned long long nt = pack2(-tau, -tau);
    float dsum = 0.f, f0 = 0.f, f1 = 0.f;
#pragma unroll
    for (int j = 0; j < 16; j++) {
        float2 v = unpack2(f32x2_add(z[j], nt));
        float t0 = fmaxf(v.x, 0.f);
        float t1 = fmaxf(v.y, 0.f);
        dsum = fmaf(t0, t0, dsum);
        dsum = fmaf(t1, t1, dsum);
        f0 += t0;
        f1 += t1;
    }
    float fT = f0 + f1;
#pragma unroll
    for (int o = 16; o > 0; o >>= 1) {
        dsum += __shfl_xor_sync(0xffffffffu, dsum, o);
        fT   += __shfl_xor_sync(0xffffffffu, fT, o);
    }

    if (lane == 0) {
        // Newton slope via finite difference against last midpoint (free fL).
        float m = (fL - fT) / (tau - mid);
        m = fmaxf(m, 0.5f);
        float d = lam - fT;
        float inv2lam = 0.5f / lam;
        y[warp] = tau + (dsum - d * d / m) * inv2lam;
    }
}

extern "C" void kernel_launch(void* const* d_in, const int* in_sizes, int n_in,
                              void* d_out, int out_size) {
    const float* x   = (const float*)d_in[0];
    const float* W   = (const float*)d_in[1];
    const float* lam = (const float*)d_in[2];
    float* y = (float*)d_out;

    int B = in_sizes[0] / DDIM;      // 128
    int N = in_sizes[1] / DDIM;      // 512 (index math assumes 512)
    int pairs = B * N;               // 65536
    int blocks = (pairs + 7) / 8;    // 8 warps / block
    moreau_tropical_kernel<<<blocks, 256>>>(x, W, lam, y, pairs);
}

// round 3
// speedup vs baseline: 2.4663x; 1.1981x over previous
#include <cuda_runtime.h>

// MoreauTropicalKernel: B=128, N=512, D=1024. One warp per (b,n) pair.
// z = x[b]+W[n] resident as 16 packed f32x2 registers.
//  - f(mid) via abs identity: f = 0.5*(sum|z-mid| + S) - (D/2)*mid
//  - Tight bracket [max z - lam, max z] (width lam)
//  - 4 bisection steps + exact-segment Newton correction (y stationary in tau,
//    slope from free finite difference vs last midpoint)
//  - Epilogue fully packed: u = t+|t| = 2*relu(t); sum|t| -> fT, sum u^2 -> 4*dsum
//    via fma.rn.f32x2 (PTX-only packed FFMA).

#define DDIM 1024
#define NDIM 512
#define NBIS 4

__device__ __forceinline__ unsigned long long f32x2_add(unsigned long long a, unsigned long long b) {
    unsigned long long r;
    asm("add.rn.f32x2 %0, %1, %2;" : "=l"(r) : "l"(a), "l"(b));
    return r;
}
__device__ __forceinline__ unsigned long long f32x2_fma(unsigned long long a, unsigned long long b, unsigned long long c) {
    unsigned long long r;
    asm("fma.rn.f32x2 %0, %1, %2, %3;" : "=l"(r) : "l"(a), "l"(b), "l"(c));
    return r;
}
__device__ __forceinline__ unsigned long long pack2(float lo, float hi) {
    unsigned long long r;
    asm("mov.b64 %0, {%1, %2};" : "=l"(r) : "f"(lo), "f"(hi));
    return r;
}
__device__ __forceinline__ float2 unpack2(unsigned long long v) {
    float2 r;
    asm("mov.b64 {%0, %1}, %2;" : "=f"(r.x), "=f"(r.y) : "l"(v));
    return r;
}

__global__ __launch_bounds__(256)
void moreau_tropical_kernel(const float* __restrict__ x,
                            const float* __restrict__ W,
                            const float* __restrict__ lamp,
                            float* __restrict__ y,
                            int total_pairs) {
    int warp = (blockIdx.x * 256 + threadIdx.x) >> 5;
    if (warp >= total_pairs) return;
    int lane = threadIdx.x & 31;
    int b = warp >> 9;           // / NDIM
    int n = warp & (NDIM - 1);
    float lam = __ldg(lamp);

    const float4* xr = (const float4*)(x + (size_t)b * DDIM);
    const float4* wr = (const float4*)(W + (size_t)n * DDIM);

    unsigned long long z[16];
    unsigned long long Sp0 = 0ull, Sp1 = 0ull;
    float mx = -3.4e38f;
#pragma unroll
    for (int j = 0; j < 8; j++) {
        float4 xv = xr[lane + 32 * j];
        float4 wv = wr[lane + 32 * j];
        unsigned long long zp0 = f32x2_add(pack2(xv.x, xv.y), pack2(wv.x, wv.y));
        unsigned long long zp1 = f32x2_add(pack2(xv.z, xv.w), pack2(wv.z, wv.w));
        z[2 * j]     = zp0;
        z[2 * j + 1] = zp1;
        Sp0 = f32x2_add(Sp0, zp0);
        Sp1 = f32x2_add(Sp1, zp1);
        float2 a = unpack2(zp0);
        float2 c = unpack2(zp1);
        mx = fmaxf(mx, fmaxf(fmaxf(a.x, a.y), fmaxf(c.x, c.y)));
    }
    float2 sv = unpack2(f32x2_add(Sp0, Sp1));
    float S = sv.x + sv.y;
#pragma unroll
    for (int o = 16; o > 0; o >>= 1) {
        S  += __shfl_xor_sync(0xffffffffu, S, o);
        mx = fmaxf(mx, __shfl_xor_sync(0xffffffffu, mx, o));
    }

    // Tight bracket: f(mx - lam) >= lam >= f(mx)
    float lo = mx - lam;
    float hi = mx;
    // f(mid) > lam  <=>  A = sum|z-mid| > 2*lam - S + D*mid
    float C = 2.f * lam - S;

    float A = 0.f, mid = lo;
#pragma unroll 1
    for (int it = 0; it < NBIS; it++) {
        mid = 0.5f * (lo + hi);
        unsigned long long nm = pack2(-mid, -mid);
        unsigned long long a0 = 0ull, a1 = 0ull;
#pragma unroll
        for (int j = 0; j < 16; j += 2) {
            unsigned long long t0 = f32x2_add(z[j + 0], nm) & 0x7FFFFFFF7FFFFFFFULL;
            unsigned long long t1 = f32x2_add(z[j + 1], nm) & 0x7FFFFFFF7FFFFFFFULL;
            a0 = f32x2_add(a0, t0);
            a1 = f32x2_add(a1, t1);
        }
        float2 av = unpack2(f32x2_add(a0, a1));
        A = av.x + av.y;
#pragma unroll
        for (int o = 16; o > 0; o >>= 1)
            A += __shfl_xor_sync(0xffffffffu, A, o);
        bool low = A > fmaf(1024.f, mid, C);
        lo = low ? mid : lo;
        hi = low ? hi : mid;
    }

    float tau = 0.5f * (lo + hi);
    // f at the last bisection midpoint, from the already-reduced A (free):
    float fL = 0.5f * (A + S) - 512.f * mid;

    // Packed epilogue: t = z - tau; |t| -> abs-sum (fT); u = t+|t| = 2*relu(t);
    // sum u^2 = 4 * sum relu^2 = 4 * dsum, accumulated with packed FFMA.
    unsigned long long nt = pack2(-tau, -tau);
    unsigned long long aA0 = 0ull, aA1 = 0ull, aU0 = 0ull, aU1 = 0ull;
#pragma unroll
    for (int j = 0; j < 16; j += 2) {
        unsigned long long t0 = f32x2_add(z[j + 0], nt);
        unsigned long long t1 = f32x2_add(z[j + 1], nt);
        unsigned long long b0 = t0 & 0x7FFFFFFF7FFFFFFFULL;
        unsigned long long b1 = t1 & 0x7FFFFFFF7FFFFFFFULL;
        aA0 = f32x2_add(aA0, b0);
        aA1 = f32x2_add(aA1, b1);
        unsigned long long u0 = f32x2_add(t0, b0);
        unsigned long long u1 = f32x2_add(t1, b1);
        aU0 = f32x2_fma(u0, u0, aU0);
        aU1 = f32x2_fma(u1, u1, aU1);
    }
    float2 Avp = unpack2(f32x2_add(aA0, aA1));
    float2 Uvp = unpack2(f32x2_add(aU0, aU1));
    float Av = Avp.x + Avp.y;   // sum |z - tau|
    float Us = Uvp.x + Uvp.y;   // 4 * sum relu^2
#pragma unroll
    for (int o = 16; o > 0; o >>= 1) {
        Av += __shfl_xor_sync(0xffffffffu, Av, o);
        Us += __shfl_xor_sync(0xffffffffu, Us, o);
    }

    if (lane == 0) {
        float fT = 0.5f * (Av + S) - 512.f * tau;   // f(tau)
        float dsum = 0.25f * Us;                     // sum relu^2
        // Newton slope via finite difference against last midpoint (free fL).
        float m = (fL - fT) / (tau - mid);
        m = fmaxf(m, 0.5f);
        float d = lam - fT;
        float inv2lam = 0.5f / lam;
        y[warp] = tau + (dsum - d * d / m) * inv2lam;
    }
}

extern "C" void kernel_launch(void* const* d_in, const int* in_sizes, int n_in,
                              void* d_out, int out_size) {
    const float* x   = (const float*)d_in[0];
    const float* W   = (const float*)d_in[1];
    const float* lam = (const float*)d_in[2];
    float* y = (float*)d_out;

    int B = in_sizes[0] / DDIM;      // 128
    int N = in_sizes[1] / DDIM;      // 512 (index math assumes 512)
    int pairs = B * N;               // 65536
    int blocks = (pairs + 7) / 8;    // 8 warps / block
    moreau_tropical_kernel<<<blocks, 256>>>(x, W, lam, y, pairs);
}

// round 4
// speedup vs baseline: 2.9308x; 1.1884x over previous
#include <cuda_runtime.h>

// MoreauTropicalKernel: B=128, N=512, D=1024. One warp per (b,n) pair.
// z = x[b]+W[n] resident as 16 packed f32x2 registers.
// f(tau) = sum relu(z-tau) is convex decreasing with f(max z) = 0 (free anchor).
// Root-find via 2 secant steps anchored at (mx, 0) -- convexity guarantees each
// iterate brackets tau* from the right -- then one epilogue pass computing
// fT and dsum, plus the exact-segment Newton correction
//   y* = y(tau) - (lam - fT)^2 / (2*lam*m),  m from free finite difference.
// f evals use the abs identity f = 0.5*(sum|z-tau| + S) - (D/2)*tau with
// packed add.rn.f32x2 / fma.rn.f32x2 (PTX-only on sm_103a).

#define DDIM 1024
#define NDIM 512

__device__ __forceinline__ unsigned long long f32x2_add(unsigned long long a, unsigned long long b) {
    unsigned long long r;
    asm("add.rn.f32x2 %0, %1, %2;" : "=l"(r) : "l"(a), "l"(b));
    return r;
}
__device__ __forceinline__ unsigned long long f32x2_fma(unsigned long long a, unsigned long long b, unsigned long long c) {
    unsigned long long r;
    asm("fma.rn.f32x2 %0, %1, %2, %3;" : "=l"(r) : "l"(a), "l"(b), "l"(c));
    return r;
}
__device__ __forceinline__ unsigned long long pack2(float lo, float hi) {
    unsigned long long r;
    asm("mov.b64 %0, {%1, %2};" : "=l"(r) : "f"(lo), "f"(hi));
    return r;
}
__device__ __forceinline__ float2 unpack2(unsigned long long v) {
    float2 r;
    asm("mov.b64 {%0, %1}, %2;" : "=f"(r.x), "=f"(r.y) : "l"(v));
    return r;
}

__global__ __launch_bounds__(256)
void moreau_tropical_kernel(const float* __restrict__ x,
                            const float* __restrict__ W,
                            const float* __restrict__ lamp,
                            float* __restrict__ y,
                            int total_pairs) {
    int warp = (blockIdx.x * 256 + threadIdx.x) >> 5;
    if (warp >= total_pairs) return;
    int lane = threadIdx.x & 31;
    int b = warp >> 9;           // / NDIM
    int n = warp & (NDIM - 1);
    float lam = __ldg(lamp);

    const float4* xr = (const float4*)(x + (size_t)b * DDIM);
    const float4* wr = (const float4*)(W + (size_t)n * DDIM);

    unsigned long long z[16];
    unsigned long long Sp0 = 0ull, Sp1 = 0ull;
    float mx = -3.4e38f;
#pragma unroll
    for (int j = 0; j < 8; j++) {
        float4 xv = xr[lane + 32 * j];
        float4 wv = wr[lane + 32 * j];
        unsigned long long zp0 = f32x2_add(pack2(xv.x, xv.y), pack2(wv.x, wv.y));
        unsigned long long zp1 = f32x2_add(pack2(xv.z, xv.w), pack2(wv.z, wv.w));
        z[2 * j]     = zp0;
        z[2 * j + 1] = zp1;
        Sp0 = f32x2_add(Sp0, zp0);
        Sp1 = f32x2_add(Sp1, zp1);
        float2 a = unpack2(zp0);
        float2 c = unpack2(zp1);
        mx = fmaxf(mx, fmaxf(fmaxf(a.x, a.y), fmaxf(c.x, c.y)));
    }
    float2 sv = unpack2(f32x2_add(Sp0, Sp1));
    float S = sv.x + sv.y;
#pragma unroll
    for (int o = 16; o > 0; o >>= 1) {
        S  += __shfl_xor_sync(0xffffffffu, S, o);
        mx = fmaxf(mx, __shfl_xor_sync(0xffffffffu, mx, o));
    }

    // --- eval helper (inlined manually twice): f(t) = 0.5*(sum|z-t| + S) - 512*t
#define EVAL_F(tauv, fout)                                                    \
    {                                                                         \
        unsigned long long nm = pack2(-(tauv), -(tauv));                      \
        unsigned long long a0 = 0ull, a1 = 0ull;                              \
        _Pragma("unroll")                                                     \
        for (int j = 0; j < 16; j += 2) {                                     \
            unsigned long long t0 = f32x2_add(z[j + 0], nm) & 0x7FFFFFFF7FFFFFFFULL; \
            unsigned long long t1 = f32x2_add(z[j + 1], nm) & 0x7FFFFFFF7FFFFFFFULL; \
            a0 = f32x2_add(a0, t0);                                           \
            a1 = f32x2_add(a1, t1);                                           \
        }                                                                     \
        float2 av = unpack2(f32x2_add(a0, a1));                               \
        float A = av.x + av.y;                                                \
        _Pragma("unroll")                                                     \
        for (int o = 16; o > 0; o >>= 1)                                      \
            A += __shfl_xor_sync(0xffffffffu, A, o);                          \
        (fout) = fmaf(-512.f, (tauv), 0.5f * (A + S));                        \
    }

    // Secant step 1: anchor (mx, 0), point (tau1 = mx - lam, f1 >= lam).
    float tau1 = mx - lam;
    float f1;
    EVAL_F(tau1, f1);
    float tau2 = mx - lam * lam / fmaxf(f1, lam);   // f1 >= lam always
    // Secant step 2: through (tau1, f1), (tau2, f2 <= lam).
    float f2;
    EVAL_F(tau2, f2);
    float d21 = fmaxf(f1 - f2, 1e-20f);
    float tau3 = tau2 - (lam - f2) * (tau2 - tau1) / d21;
    tau3 = fminf(fmaxf(tau3, tau1), tau2);

    // Epilogue at tau3: t = z - tau3; |t| -> abs-sum (f3 via identity);
    // u = t+|t| = 2*relu(t); sum u^2 = 4*dsum via packed FFMA.
    unsigned long long nt = pack2(-tau3, -tau3);
    unsigned long long aA0 = 0ull, aA1 = 0ull, aU0 = 0ull, aU1 = 0ull;
#pragma unroll
    for (int j = 0; j < 16; j += 2) {
        unsigned long long t0 = f32x2_add(z[j + 0], nt);
        unsigned long long t1 = f32x2_add(z[j + 1], nt);
        unsigned long long b0 = t0 & 0x7FFFFFFF7FFFFFFFULL;
        unsigned long long b1 = t1 & 0x7FFFFFFF7FFFFFFFULL;
        aA0 = f32x2_add(aA0, b0);
        aA1 = f32x2_add(aA1, b1);
        unsigned long long u0 = f32x2_add(t0, b0);
        unsigned long long u1 = f32x2_add(t1, b1);
        aU0 = f32x2_fma(u0, u0, aU0);
        aU1 = f32x2_fma(u1, u1, aU1);
    }
    float2 Avp = unpack2(f32x2_add(aA0, aA1));
    float2 Uvp = unpack2(f32x2_add(aU0, aU1));
    float Av = Avp.x + Avp.y;   // sum |z - tau3|
    float Us = Uvp.x + Uvp.y;   // 4 * sum relu^2
#pragma unroll
    for (int o = 16; o > 0; o >>= 1) {
        Av += __shfl_xor_sync(0xffffffffu, Av, o);
        Us += __shfl_xor_sync(0xffffffffu, Us, o);
    }

    if (lane == 0) {
        float f3 = fmaf(-512.f, tau3, 0.5f * (Av + S));
        float dsum = 0.25f * Us;
        // Slope (positive) from free finite difference (tau2, f2) vs (tau3, f3).
        float m = (f3 - f2) / fmaxf(tau2 - tau3, 1e-20f);
        m = fmaxf(m, 0.5f);
        float d = lam - f3;
        float inv2lam = 0.5f / lam;
        y[warp] = tau3 + (dsum - d * d / m) * inv2lam;
    }
#undef EVAL_F
}

extern "C" void kernel_launch(void* const* d_in, const int* in_sizes, int n_in,
                              void* d_out, int out_size) {
    const float* x   = (const float*)d_in[0];
    const float* W   = (const float*)d_in[1];
    const float* lam = (const float*)d_in[2];
    float* y = (float*)d_out;

    int B = in_sizes[0] / DDIM;      // 128
    int N = in_sizes[1] / DDIM;      // 512 (index math assumes 512)
    int pairs = B * N;               // 65536
    int blocks = (pairs + 7) / 8;    // 8 warps / block
    moreau_tropical_kernel<<<blocks, 256>>>(x, W, lam, y, pairs);
}

// round 5
// speedup vs baseline: 3.2356x; 1.1040x over previous
#include <cuda_runtime.h>

// MoreauTropicalKernel: B=128, N=512, D=1024. One warp per (b,n) pair.
// z = x[b]+W[n] resident as 16 packed f32x2 registers.
//  - f(tau) = sum relu(z-tau), convex decreasing, f(max z) = 0 (free anchor).
//  - One dual-eval pass at taua=mx-lam, taub=mx-lam/2 (abs identity
//    f = 0.5*(sum|z-t| + S) - 512*t), then inverse quadratic interpolation
//    through (taua,fa),(taub,fb),(mx,0) -> tau3. Denoms >= lam/2, no guards.
//  - Epilogue at tau3 computes f3, dsum = sum relu^2, and the EXACT active
//    count k = #{z >= tau3} (PRMT sign-byte trick); correction
//    y = tau3 + (dsum - (lam-f3)^2/k)/(2 lam) is exact on tau3's segment.
//  - All warp reductions use single-instruction REDUX (fixed-point for float
//    sums, order-preserving uint map for max) instead of 5-shfl chains.

#define DDIM 1024
#define NDIM 512
#define ABSMASK 0x7FFFFFFF7FFFFFFFULL

__device__ __forceinline__ unsigned long long f32x2_add(unsigned long long a, unsigned long long b) {
    unsigned long long r;
    asm("add.rn.f32x2 %0, %1, %2;" : "=l"(r) : "l"(a), "l"(b));
    return r;
}
__device__ __forceinline__ unsigned long long f32x2_fma(unsigned long long a, unsigned long long b, unsigned long long c) {
    unsigned long long r;
    asm("fma.rn.f32x2 %0, %1, %2, %3;" : "=l"(r) : "l"(a), "l"(b), "l"(c));
    return r;
}
__device__ __forceinline__ unsigned long long pack2(float lo, float hi) {
    unsigned long long r;
    asm("mov.b64 %0, {%1, %2};" : "=l"(r) : "f"(lo), "f"(hi));
    return r;
}
__device__ __forceinline__ float2 unpack2(unsigned long long v) {
    float2 r;
    asm("mov.b64 {%0, %1}, %2;" : "=f"(r.x), "=f"(r.y) : "l"(v));
    return r;
}
// Two-bit negative-sign pair from a packed f32x2 word: byte0 = (lo<0), byte1 = (hi<0).
__device__ __forceinline__ unsigned int negpair(unsigned long long t) {
    unsigned int lo, hi, r;
    asm("mov.b64 {%0, %1}, %2;" : "=r"(lo), "=r"(hi) : "l"(t));
    asm("prmt.b32 %0, %1, %2, 0x00FB;" : "=r"(r) : "r"(lo), "r"(hi));
    return r & 0x00000101u;
}
// Fixed-point warp sum via REDUX.SUM (exact integer add, deterministic).
__device__ __forceinline__ float redux_fsum(float v, float scale, float inv) {
    int i = __float2int_rn(v * scale);
    unsigned s = __reduce_add_sync(0xffffffffu, (unsigned)i);
    return (float)(int)s * inv;
}
// Order-preserving float<->uint map for REDUX.MAX.
__device__ __forceinline__ unsigned fmap(float f) {
    unsigned u = __float_as_uint(f);
    return (u & 0x80000000u) ? ~u : (u | 0x80000000u);
}
__device__ __forceinline__ float funmap(unsigned m) {
    unsigned u = (m & 0x80000000u) ? (m ^ 0x80000000u) : ~m;
    return __uint_as_float(u);
}

__global__ __launch_bounds__(256)
void moreau_tropical_kernel(const float* __restrict__ x,
                            const float* __restrict__ W,
                            const float* __restrict__ lamp,
                            float* __restrict__ y,
                            int total_pairs) {
    int warp = (blockIdx.x * 256 + threadIdx.x) >> 5;
    if (warp >= total_pairs) return;
    int lane = threadIdx.x & 31;
    int b = warp >> 9;           // / NDIM
    int n = warp & (NDIM - 1);
    float lam = __ldg(lamp);

    const float4* xr = (const float4*)(x + (size_t)b * DDIM);
    const float4* wr = (const float4*)(W + (size_t)n * DDIM);

    unsigned long long z[16];
    unsigned long long Sp0 = 0ull, Sp1 = 0ull;
    float mx = -3.4e38f;
#pragma unroll
    for (int j = 0; j < 8; j++) {
        float4 xv = xr[lane + 32 * j];
        float4 wv = wr[lane + 32 * j];
        unsigned long long zp0 = f32x2_add(pack2(xv.x, xv.y), pack2(wv.x, wv.y));
        unsigned long long zp1 = f32x2_add(pack2(xv.z, xv.w), pack2(wv.z, wv.w));
        z[2 * j]     = zp0;
        z[2 * j + 1] = zp1;
        Sp0 = f32x2_add(Sp0, zp0);
        Sp1 = f32x2_add(Sp1, zp1);
        float2 a = unpack2(zp0);
        float2 c = unpack2(zp1);
        mx = fmaxf(mx, fmaxf(fmaxf(a.x, a.y), fmaxf(c.x, c.y)));
    }
    float2 sv = unpack2(f32x2_add(Sp0, Sp1));
    float S = redux_fsum(sv.x + sv.y, 131072.0f, 7.62939453e-6f);   // 2^17
    mx = funmap(__reduce_max_sync(0xffffffffu, fmap(mx)));

    // Dual f-eval pass at taua = mx - lam and taub = mx - lam/2 (abs identity).
    float taua = mx - lam;
    float taub = mx - 0.5f * lam;
    unsigned long long na = pack2(-taua, -taua);
    unsigned long long hb = pack2(-0.5f * lam, -0.5f * lam);   // t_b = t_a - lam/2
    unsigned long long aa0 = 0ull, aa1 = 0ull, ab0 = 0ull, ab1 = 0ull;
#pragma unroll
    for (int j = 0; j < 16; j += 2) {
        unsigned long long ta0 = f32x2_add(z[j + 0], na);
        unsigned long long ta1 = f32x2_add(z[j + 1], na);
        unsigned long long tb0 = f32x2_add(ta0, hb);
        unsigned long long tb1 = f32x2_add(ta1, hb);
        aa0 = f32x2_add(aa0, ta0 & ABSMASK);
        aa1 = f32x2_add(aa1, ta1 & ABSMASK);
        ab0 = f32x2_add(ab0, tb0 & ABSMASK);
        ab1 = f32x2_add(ab1, tb1 & ABSMASK);
    }
    float2 av = unpack2(f32x2_add(aa0, aa1));
    float2 bv = unpack2(f32x2_add(ab0, ab1));
    float Aa = redux_fsum(av.x + av.y, 65536.0f, 1.52587890625e-5f);  // 2^16
    float Ab = redux_fsum(bv.x + bv.y, 65536.0f, 1.52587890625e-5f);
    float fa = fmaf(-512.f, taua, 0.5f * (Aa + S));
    float fb = fmaf(-512.f, taub, 0.5f * (Ab + S));

    // Inverse quadratic interpolation through (taua,fa),(taub,fb),(mx,0) for f=lam.
    // fa >= lam, fb >= lam/2, fa-fb >= lam/2 (slope >= 1 while f>0): no guards.
    float la = lam - fa;
    float lb = lam - fb;
    float wa = __fdividef(lb * lam, (fa - fb) * fa);
    float wb = __fdividef(la * lam, (fb - fa) * fb);
    float wm = __fdividef(la * lb, fa * fb);
    float tau3 = taua * wa + taub * wb + mx * wm;
    tau3 = fminf(fmaxf(tau3, taua), mx);

    // Epilogue at tau3: f3 (abs identity), dsum via u = t+|t| = 2*relu,
    // and exact active count k = #{z >= tau3}.
    unsigned long long nt = pack2(-tau3, -tau3);
    unsigned long long aA0 = 0ull, aA1 = 0ull, aU0 = 0ull, aU1 = 0ull;
    unsigned int cnt = 0u;
#pragma unroll
    for (int j = 0; j < 16; j += 2) {
        unsigned long long t0 = f32x2_add(z[j + 0], nt);
        unsigned long long t1 = f32x2_add(z[j + 1], nt);
        unsigned long long b0 = t0 & ABSMASK;
        unsigned long long b1 = t1 & ABSMASK;
        aA0 = f32x2_add(aA0, b0);
        aA1 = f32x2_add(aA1, b1);
        unsigned long long u0 = f32x2_add(t0, b0);
        unsigned long long u1 = f32x2_add(t1, b1);
        aU0 = f32x2_fma(u0, u0, aU0);
        aU1 = f32x2_fma(u1, u1, aU1);
        cnt += negpair(t0);
        cnt += negpair(t1);
    }
    float2 Avp = unpack2(f32x2_add(aA0, aA1));
    float2 Uvp = unpack2(f32x2_add(aU0, aU1));
    float Av = redux_fsum(Avp.x + Avp.y, 65536.0f, 1.52587890625e-5f);   // 2^16
    float Us = redux_fsum(Uvp.x + Uvp.y, 1048576.0f, 9.5367431640625e-7f); // 2^20
    unsigned neg = __reduce_add_sync(0xffffffffu, (cnt & 0xFFu) + (cnt >> 8));
    float kf = (float)(1024u - neg);   // k >= 1 always (element at mx has t >= 0)

    if (lane == 0) {
        float f3 = fmaf(-512.f, tau3, 0.5f * (Av + S));
        float dsum = 0.25f * Us;
        float d = lam - f3;
        float corr = __fdividef(d * d, kf);
        y[warp] = tau3 + (dsum - corr) * __fdividef(0.5f, lam);
    }
}

extern "C" void kernel_launch(void* const* d_in, const int* in_sizes, int n_in,
                              void* d_out, int out_size) {
    const float* x   = (const float*)d_in[0];
    const float* W   = (const float*)d_in[1];
    const float* lam = (const float*)d_in[2];
    float* y = (float*)d_out;

    int B = in_sizes[0] / DDIM;      // 128
    int N = in_sizes[1] / DDIM;      // 512 (index math assumes 512)
    int pairs = B * N;               // 65536
    int blocks = (pairs + 7) / 8;    // 8 warps / block
    moreau_tropical_kernel<<<blocks, 256>>>(x, W, lam, y, pairs);
}

// round 7
// speedup vs baseline: 3.8335x; 1.1848x over previous
#include <cuda_runtime.h>

// MoreauTropicalKernel: B=128, N=512, D=1024. One warp per (b,n) pair.
// z = x[b]+W[n] resident as 16 packed f32x2 registers.
// Two full-array passes after setup:
//  Pass1 @ taua = mx - lam:  u = t + |t| = 2*relu(t)  ->  fa = sum(u)/2,
//    and exact active count ka = #{z >= taua} via PRMT sign + dp4a.
//    Exact Newton step (convex, from the left): tau2 = taua + (fa-lam)/ka <= tau*.
//  Pass2 @ tau2 (epilogue): f2 = sum(u)/2, dsum = sum(u^2)/4, k2.
//    Exact-segment closed form: y = tau2 + (dsum - (lam-f2)^2/k2) / (2*lam),
//    exact when no breakpoint lies in (tau2, tau*).
// Structural guarantees: fa >= lam, ka >= 1, k2 >= 1 (max element alone).
// Warp reductions: single-instruction REDUX (fixed-point for float sums,
// order-preserving uint map for max).

#define DDIM 1024
#define NDIM 512
#define ABSMASK 0x7FFFFFFF7FFFFFFFULL

typedef unsigned long long u64;

__device__ __forceinline__ u64 f32x2_add(u64 a, u64 b) {
    u64 r; asm("add.rn.f32x2 %0, %1, %2;" : "=l"(r) : "l"(a), "l"(b)); return r;
}
__device__ __forceinline__ u64 f32x2_fma(u64 a, u64 b, u64 c) {
    u64 r; asm("fma.rn.f32x2 %0, %1, %2, %3;" : "=l"(r) : "l"(a), "l"(b), "l"(c)); return r;
}
__device__ __forceinline__ u64 pack2(float lo, float hi) {
    u64 r; asm("mov.b64 %0, {%1, %2};" : "=l"(r) : "f"(lo), "f"(hi)); return r;
}
__device__ __forceinline__ float2 unpack2(u64 v) {
    float2 r; asm("mov.b64 {%0, %1}, %2;" : "=f"(r.x), "=f"(r.y) : "l"(v)); return r;
}
// cnt += -2 * (#negative floats in packed word t):
// PRMT replicates each half's sign byte twice; dp4a sums the four s8 lanes.
__device__ __forceinline__ void dp4a_sgn(u64 t, int& cnt) {
    unsigned lo, hi, p;
    asm("mov.b64 {%0, %1}, %2;" : "=r"(lo), "=r"(hi) : "l"(t));
    asm("prmt.b32 %0, %1, %2, 0xFBFB;" : "=r"(p) : "r"(lo), "r"(hi));
    asm("dp4a.s32.s32 %0, %1, %2, %0;" : "+r"(cnt) : "r"(p), "r"(0x01010101));
}
// Fixed-point warp sum via REDUX.SUM (exact deterministic integer add).
__device__ __forceinline__ float redux_fsum(float v, float scale, float inv) {
    int i = __float2int_rn(v * scale);
    unsigned s = __reduce_add_sync(0xffffffffu, (unsigned)i);
    return (float)(int)s * inv;
}
__device__ __forceinline__ unsigned fmap(float f) {
    unsigned u = __float_as_uint(f);
    return (u & 0x80000000u) ? ~u : (u | 0x80000000u);
}
__device__ __forceinline__ float funmap(unsigned m) {
    unsigned u = (m & 0x80000000u) ? (m ^ 0x80000000u) : ~m;
    return __uint_as_float(u);
}

__global__ __launch_bounds__(256, 5)
void moreau_tropical_kernel(const float* __restrict__ x,
                            const float* __restrict__ W,
                            const float* __restrict__ lamp,
                            float* __restrict__ y,
                            int total_pairs) {
    int warp = (blockIdx.x * 256 + threadIdx.x) >> 5;
    if (warp >= total_pairs) return;
    int lane = threadIdx.x & 31;
    int b = warp >> 9;           // / NDIM
    int n = warp & (NDIM - 1);
    float lam = __ldg(lamp);

    const float4* xr = (const float4*)(x + (size_t)b * DDIM);
    const float4* wr = (const float4*)(W + (size_t)n * DDIM);

    u64 z[16];
    float mx = -3.4e38f;
#pragma unroll
    for (int j = 0; j < 8; j++) {
        float4 xv = xr[lane + 32 * j];
        float4 wv = wr[lane + 32 * j];
        u64 zp0 = f32x2_add(pack2(xv.x, xv.y), pack2(wv.x, wv.y));
        u64 zp1 = f32x2_add(pack2(xv.z, xv.w), pack2(wv.z, wv.w));
        z[2 * j]     = zp0;
        z[2 * j + 1] = zp1;
        float2 a = unpack2(zp0);
        float2 c = unpack2(zp1);
        mx = fmaxf(mx, fmaxf(fmaxf(a.x, a.y), fmaxf(c.x, c.y)));
    }
    mx = funmap(__reduce_max_sync(0xffffffffu, fmap(mx)));

    // Pass 1 @ taua = mx - lam: u = t + |t| = 2*relu(t); fa = sum(u)/2; ka count.
    float taua = mx - lam;
    u64 na = pack2(-taua, -taua);
    u64 ua0 = 0ull, ua1 = 0ull;
    int ca = 0;
#pragma unroll
    for (int j = 0; j < 16; j += 2) {
        u64 t0 = f32x2_add(z[j + 0], na);
        u64 t1 = f32x2_add(z[j + 1], na);
        u64 b0 = t0 & ABSMASK;
        u64 b1 = t1 & ABSMASK;
        ua0 = f32x2_add(ua0, f32x2_add(t0, b0));
        ua1 = f32x2_add(ua1, f32x2_add(t1, b1));
        dp4a_sgn(t0, ca);
        dp4a_sgn(t1, ca);
    }
    float2 uav = unpack2(f32x2_add(ua0, ua1));
    float fa = 0.5f * redux_fsum(uav.x + uav.y, 1048576.0f, 9.5367431640625e-7f); // 2^20
    int cta = (int)__reduce_add_sync(0xffffffffu, (unsigned)ca);   // -2 * #neg
    float ka = (float)(1024 + (cta >> 1));                         // >= 1

    // Exact Newton step from the left (convex): tau2 <= tau*.
    float tau2 = taua + __fdividef(fa - lam, ka);
    tau2 = fminf(fmaxf(tau2, taua), mx);

    // Pass 2 (epilogue) @ tau2: f2, dsum = sum relu^2, k2.
    u64 nt = pack2(-tau2, -tau2);
    u64 us0 = 0ull, us1 = 0ull, q0 = 0ull, q1 = 0ull;
    int c2 = 0;
#pragma unroll
    for (int j = 0; j < 16; j += 2) {
        u64 t0 = f32x2_add(z[j + 0], nt);
        u64 t1 = f32x2_add(z[j + 1], nt);
        u64 b0 = t0 & ABSMASK;
        u64 b1 = t1 & ABSMASK;
        u64 u0 = f32x2_add(t0, b0);
        u64 u1 = f32x2_add(t1, b1);
        us0 = f32x2_add(us0, u0);
        us1 = f32x2_add(us1, u1);
        q0 = f32x2_fma(u0, u0, q0);
        q1 = f32x2_fma(u1, u1, q1);
        dp4a_sgn(t0, c2);
        dp4a_sgn(t1, c2);
    }
    float2 usv = unpack2(f32x2_add(us0, us1));
    float2 qv  = unpack2(f32x2_add(q0, q1));
    float f2 = 0.5f * redux_fsum(usv.x + usv.y, 1048576.0f, 9.5367431640625e-7f);  // 2^20
    float Us = redux_fsum(qv.x + qv.y, 2097152.0f, 4.76837158203125e-7f);          // 2^21
    int ct2 = (int)__reduce_add_sync(0xffffffffu, (unsigned)c2);
    float k2 = (float)(1024 + (ct2 >> 1));                         // >= 1

    if (lane == 0) {
        float dsum = 0.25f * Us;
        float d = lam - f2;
        float corr = __fdividef(d * d, k2);
        y[warp] = tau2 + (dsum - corr) * __fdividef(0.5f, lam);
    }
}

extern "C" void kernel_launch(void* const* d_in, const int* in_sizes, int n_in,
                              void* d_out, int out_size) {
    const float* x   = (const float*)d_in[0];
    const float* W   = (const float*)d_in[1];
    const float* lam = (const float*)d_in[2];
    float* y = (float*)d_out;

    int B = in_sizes[0] / DDIM;      // 128
    int N = in_sizes[1] / DDIM;      // 512 (index math assumes 512)
    int pairs = B * N;               // 65536
    int blocks = (pairs + 7) / 8;    // 8 warps / block
    moreau_tropical_kernel<<<blocks, 256>>>(x, W, lam, y, pairs);
}